// round 1
// baseline (speedup 1.0000x reference)
#include <cuda_runtime.h>
#include <math.h>

#define D 128
#define NMAX 210048

// Scratch: Q, K, V, attention-out  (4 * NMAX * 128 floats ~ 430 MB, static — no allocs)
__device__ float g_scr[(size_t)4 * NMAX * D];
__device__ int g_ws16[20002];
__device__ int g_ws64[8002];

// ---------------------------------------------------------------------------
// Window-start builder: tokens of window w are the contiguous range
// [ws[w], ws[w+1]) because flat_pos is strictly increasing.
// ---------------------------------------------------------------------------
__global__ void build_ws(const int* __restrict__ fp, int n, int L,
                         int* __restrict__ ws, int nw)
{
    int i = blockIdx.x * blockDim.x + threadIdx.x;
    if (i < n) {
        int w = fp[i] / L;
        if (i == 0 || fp[i - 1] / L != w) ws[w] = i;
    }
    if (i == 0) ws[nw] = n;
}

// ---------------------------------------------------------------------------
// Tiled GEMM: OUT[row(t)] = X[src(t)] (+POS[fp(t)]) @ W^T + bias
//   64 tokens x 128 channels per block, K = 128.
//   As: 64x129 (padded), Bs: 128x129 (k-major, padded) -> conflict-light.
//   Thread (tx,ty): 4 tokens x 8 channels (channels tx, tx+16, ..., tx+112).
// ---------------------------------------------------------------------------
template <bool ADD_POS>
__global__ __launch_bounds__(256)
void gemm_tok(const float* __restrict__ X, const int* __restrict__ gidx,
              const float* __restrict__ POS, const int* __restrict__ fp,
              const float* __restrict__ W, const float* __restrict__ bias,
              float* __restrict__ OUT, const int* __restrict__ sidx, int ntok)
{
    extern __shared__ float sm[];
    float* As = sm;              // 64 x 129
    float* Bs = sm + 64 * 129;   // 128 x 129, Bs[k*129 + c] = W[c*128 + k]
    const int tid = threadIdx.x;
    const int tb = blockIdx.x * 64;

    // Load W tile (transposed into k-major)
#pragma unroll
    for (int it = 0; it < 16; it++) {
        int idx = tid + it * 256;          // 0..4095
        int c  = idx >> 5;                 // 0..127
        int k4 = (idx & 31) << 2;          // 0,4,...,124
        float4 w4 = *(const float4*)(W + c * D + k4);
        Bs[(k4 + 0) * 129 + c] = w4.x;
        Bs[(k4 + 1) * 129 + c] = w4.y;
        Bs[(k4 + 2) * 129 + c] = w4.z;
        Bs[(k4 + 3) * 129 + c] = w4.w;
    }
    // Load A tile (gather + optional pos add), zero-pad tail tokens
#pragma unroll
    for (int it = 0; it < 8; it++) {
        int idx = tid + it * 256;          // 0..2047
        int r  = idx >> 5;                 // 0..63
        int c4 = (idx & 31) << 2;
        int t  = tb + r;
        float4 v = make_float4(0.f, 0.f, 0.f, 0.f);
        if (t < ntok) {
            int src = gidx ? gidx[t] : t;
            v = *(const float4*)(X + (size_t)src * D + c4);
            if (ADD_POS) {
                float4 p = *(const float4*)(POS + (size_t)fp[t] * D + c4);
                v.x += p.x; v.y += p.y; v.z += p.z; v.w += p.w;
            }
        }
        As[r * 129 + c4 + 0] = v.x;
        As[r * 129 + c4 + 1] = v.y;
        As[r * 129 + c4 + 2] = v.z;
        As[r * 129 + c4 + 3] = v.w;
    }
    __syncthreads();

    const int tx = tid & 15;
    const int ty = tid >> 4;
    float acc[4][8];
#pragma unroll
    for (int u = 0; u < 4; u++)
#pragma unroll
        for (int v = 0; v < 8; v++) acc[u][v] = 0.f;

    const float* Ap = As + ty * 4 * 129;
    const float* Bp = Bs + tx;
#pragma unroll 8
    for (int k = 0; k < D; k++) {
        float a0 = Ap[k];
        float a1 = Ap[129 + k];
        float a2 = Ap[258 + k];
        float a3 = Ap[387 + k];
        const float* bk = Bp + k * 129;
#pragma unroll
        for (int v = 0; v < 8; v++) {
            float b = bk[v * 16];
            acc[0][v] += a0 * b;
            acc[1][v] += a1 * b;
            acc[2][v] += a2 * b;
            acc[3][v] += a3 * b;
        }
    }

#pragma unroll
    for (int u = 0; u < 4; u++) {
        int t = tb + ty * 4 + u;
        if (t < ntok) {
            int row = sidx ? sidx[t] : t;
            float* o = OUT + (size_t)row * D;
#pragma unroll
            for (int v = 0; v < 8; v++) {
                int c = tx + v * 16;
                o[c] = acc[u][v] + bias[c];
            }
        }
    }
}

// ---------------------------------------------------------------------------
// Attention: one block per window, warp h handles head h (d = 16).
// K/V rows for the window are contiguous tokens [t0, t0+len).
// ---------------------------------------------------------------------------
template <int L>
__global__ __launch_bounds__(256)
void attn_kernel(const float* __restrict__ Q, const float* __restrict__ K,
                 const float* __restrict__ V, const int* __restrict__ ws,
                 float* __restrict__ AO)
{
    extern __shared__ float sm[];
    float* Ks = sm;                 // L x 129
    float* Vs = sm + L * 129;       // L x 129
    float* pb = Vs + L * 129;       // 8 warps x 64 probs
    const int w = blockIdx.x;
    const int t0 = ws[w];
    const int len = ws[w + 1] - t0;
    const int tid = threadIdx.x;

    for (int idx = tid; idx < len * D; idx += 256) {
        int r = idx >> 7, c = idx & 127;
        Ks[r * 129 + c] = K[(size_t)(t0 + r) * D + c];
        Vs[r * 129 + c] = V[(size_t)(t0 + r) * D + c];
    }
    __syncthreads();

    const int h = tid >> 5;
    const int lane = tid & 31;
    const int cb = h * 16;
    const int dd = lane & 15, half = lane >> 4;
    float* pbw = pb + h * 64;
    const float* kr0 = Ks + min(lane, len - 1) * 129 + cb;
    const float* kr1 = (L > 32) ? (Ks + min(lane + 32, len - 1) * 129 + cb) : kr0;

    for (int i = 0; i < len; i++) {
        float qv = 0.f;
        if (lane < 16) qv = Q[(size_t)(t0 + i) * D + cb + lane];
        float s0 = 0.f, s1 = 0.f;
#pragma unroll
        for (int d = 0; d < 16; d++) {
            float qd = __shfl_sync(0xffffffffu, qv, d);
            s0 += qd * kr0[d];
            if (L > 32) s1 += qd * kr1[d];
        }
        s0 = (lane < len) ? s0 * 0.25f : -1e30f;                    // scale = 1/sqrt(16)
        s1 = (L > 32 && lane + 32 < len) ? s1 * 0.25f : -1e30f;
        float m = fmaxf(s0, s1);
#pragma unroll
        for (int o = 16; o > 0; o >>= 1)
            m = fmaxf(m, __shfl_xor_sync(0xffffffffu, m, o));
        float p0 = (lane < len) ? __expf(s0 - m) : 0.f;
        float p1 = (L > 32 && lane + 32 < len) ? __expf(s1 - m) : 0.f;
        float dsum = p0 + p1;
#pragma unroll
        for (int o = 16; o > 0; o >>= 1)
            dsum += __shfl_xor_sync(0xffffffffu, dsum, o);
        float inv = 1.f / dsum;
        pbw[lane] = p0 * inv;
        if (L > 32) pbw[lane + 32] = p1 * inv;
        __syncwarp();

        float accv = 0.f;
        for (int j = half; j < len; j += 2)
            accv += pbw[j] * Vs[j * 129 + cb + dd];
        accv += __shfl_xor_sync(0xffffffffu, accv, 16);
        if (lane < 16) AO[(size_t)(t0 + i) * D + cb + lane] = accv;
        __syncwarp();
    }
}

// ---------------------------------------------------------------------------
extern "C" void kernel_launch(void* const* d_in, const int* in_sizes, int n_in,
                              void* d_out, int out_size)
{
    const float* feat  = (const float*)d_in[0];
    const float* pos16 = (const float*)d_in[1];
    const float* pos64 = (const float*)d_in[2];
    const float* Win   = (const float*)d_in[3];
    const float* bin   = (const float*)d_in[4];
    const float* Wout  = (const float*)d_in[5];
    const float* bout  = (const float*)d_in[6];
    const int* vox16 = (const int*)d_in[7];
    const int* fp16  = (const int*)d_in[8];
    const int* vox64 = (const int*)d_in[9];
    const int* fp64  = (const int*)d_in[10];
    const int n16  = in_sizes[7];
    const int n64  = in_sizes[9];
    const int nw16 = in_sizes[1] / (16 * D);
    const int nw64 = in_sizes[2] / (64 * D);
    float* out = (float*)d_out;

    float* scr = nullptr;
    cudaGetSymbolAddress((void**)&scr, g_scr);
    int* ws16 = nullptr; cudaGetSymbolAddress((void**)&ws16, g_ws16);
    int* ws64 = nullptr; cudaGetSymbolAddress((void**)&ws64, g_ws64);
    float* Qb = scr;
    float* Kb = scr + (size_t)NMAX * D;
    float* Vb = scr + (size_t)2 * NMAX * D;
    float* AO = scr + (size_t)3 * NMAX * D;

    const size_t gsm   = (64 * 129 + 128 * 129) * sizeof(float);   // 99072 B
    const size_t asm16 = (2 * 16 * 129 + 8 * 64) * sizeof(float);
    const size_t asm64 = (2 * 64 * 129 + 8 * 64) * sizeof(float);  // 68096 B
    cudaFuncSetAttribute(gemm_tok<true>,  cudaFuncAttributeMaxDynamicSharedMemorySize, (int)gsm);
    cudaFuncSetAttribute(gemm_tok<false>, cudaFuncAttributeMaxDynamicSharedMemorySize, (int)gsm);
    cudaFuncSetAttribute(attn_kernel<64>, cudaFuncAttributeMaxDynamicSharedMemorySize, (int)asm64);

    build_ws<<<(n16 + 255) / 256, 256>>>(fp16, n16, 16, ws16, nw16);
    build_ws<<<(n64 + 255) / 256, 256>>>(fp64, n64, 64, ws64, nw64);

    const int gb16 = (n16 + 63) / 64, gb64 = (n64 + 63) / 64;
    const size_t off = (size_t)n16 * D;

    // QKV projections (valid tokens only; Q/K input = gather(feat)+pos, V input = gather(feat))
    gemm_tok<true ><<<gb16, 256, gsm>>>(feat, vox16, pos16, fp16, Win,           bin,       Qb,       nullptr, n16);
    gemm_tok<true ><<<gb16, 256, gsm>>>(feat, vox16, pos16, fp16, Win + 128 * D, bin + 128, Kb,       nullptr, n16);
    gemm_tok<false><<<gb16, 256, gsm>>>(feat, vox16, nullptr, nullptr, Win + 256 * D, bin + 256, Vb,  nullptr, n16);
    gemm_tok<true ><<<gb64, 256, gsm>>>(feat, vox64, pos64, fp64, Win,           bin,       Qb + off, nullptr, n64);
    gemm_tok<true ><<<gb64, 256, gsm>>>(feat, vox64, pos64, fp64, Win + 128 * D, bin + 128, Kb + off, nullptr, n64);
    gemm_tok<false><<<gb64, 256, gsm>>>(feat, vox64, nullptr, nullptr, Win + 256 * D, bin + 256, Vb + off, nullptr, n64);

    // Per-window attention
    attn_kernel<16><<<nw16, 256, asm16>>>(Qb, Kb, Vb, ws16, AO);
    attn_kernel<64><<<nw64, 256, asm64>>>(Qb + off, Kb + off, Vb + off, ws64, AO + off);

    // Output projection, scattered straight into d_out (voxel indices cover all rows)
    gemm_tok<false><<<gb16, 256, gsm>>>(AO,       nullptr, nullptr, nullptr, Wout, bout, out, vox16, n16);
    gemm_tok<false><<<gb64, 256, gsm>>>(AO + off, nullptr, nullptr, nullptr, Wout, bout, out, vox64, n64);
}